// round 1
// baseline (speedup 1.0000x reference)
#include <cuda_runtime.h>

#define DD 4096

typedef unsigned long long u64;

__device__ float g_dev[DD];

__global__ void compute_g_kernel(const float* __restrict__ eps,
                                 const float* __restrict__ g_mu,
                                 const float* __restrict__ g_rho) {
    int i = blockIdx.x * blockDim.x + threadIdx.x;
    if (i < DD) {
        float r = g_rho[i];
        g_dev[i] = g_mu[i] + log1pf(expf(r)) * eps[i];
    }
}

__device__ __forceinline__ u64 ADD2(u64 a, u64 b){ u64 c; asm("add.rn.f32x2 %0, %1, %2;" : "=l"(c) : "l"(a), "l"(b)); return c; }
__device__ __forceinline__ u64 SUB2(u64 a, u64 b){ u64 c; asm("sub.rn.f32x2 %0, %1, %2;" : "=l"(c) : "l"(a), "l"(b)); return c; }
__device__ __forceinline__ u64 MUL2(u64 a, u64 b){ u64 c; asm("mul.rn.f32x2 %0, %1, %2;" : "=l"(c) : "l"(a), "l"(b)); return c; }
__device__ __forceinline__ u64 PACK2(float lo, float hi){ u64 c; asm("mov.b64 %0, {%1, %2};" : "=l"(c) : "f"(lo), "f"(hi)); return c; }
__device__ __forceinline__ float2 UNPK(u64 v){ float2 r; asm("mov.b64 {%0, %1}, %2;" : "=f"(r.x), "=f"(r.y) : "l"(v)); return r; }

// XOR swizzle on the float2 element index: conflict-free for all three
// access layouts used below (verified per half-warp bank-group analysis).
__device__ __forceinline__ int SWZ(int i){ return i ^ ((i >> 4) & 15); }

// Radix-16 FWHT over the register index k (4 butterfly stages), packed
// over two rows per f32x2 lane.
__device__ __forceinline__ void fwht16(u64 v[16]) {
#pragma unroll
    for (int s = 0; s < 4; s++) {
        const int h = 1 << s;
#pragma unroll
        for (int q = 0; q < 16; q += 2*h) {
#pragma unroll
            for (int j = 0; j < h; j++) {
                u64 a = v[q+j], b = v[q+j+h];
                v[q+j]   = ADD2(a, b);
                v[q+j+h] = SUB2(a, b);
            }
        }
    }
}

// y_row = s1 * FWHT( g * FWHT( s2 * x_row ) )
// FWHT_4096 split into 3 radix-16 passes over element-bit groups:
//   X: bits {0,1,10,11}  (coalesced float4 global I/O)
//   Y: bits {2,3,4,5}
//   Z: bits {6,7,8,9}    (fused: FWHT1 tail + g + FWHT2 head)
__global__ __launch_bounds__(256)
void whvi_kernel(const float* __restrict__ x,
                 const float* __restrict__ s1,
                 const float* __restrict__ s2,
                 float* __restrict__ out) {
    __shared__ u64 sm[DD];
    const int t = threadIdx.x;
    const long long rowA = 2LL * blockIdx.x;
    const float* xa = x + rowA * DD;
    const float* xb = xa + DD;
    u64 v[16];

    // ---- P1: layout X, fused global load + s2 scale ----
#pragma unroll
    for (int m = 0; m < 4; m++) {
        int base = 4*t + 1024*m;
        float4 a = *reinterpret_cast<const float4*>(xa + base);
        float4 b = *reinterpret_cast<const float4*>(xb + base);
        float4 s = *reinterpret_cast<const float4*>(s2 + base);
        v[4*m+0] = PACK2(a.x*s.x, b.x*s.x);
        v[4*m+1] = PACK2(a.y*s.y, b.y*s.y);
        v[4*m+2] = PACK2(a.z*s.z, b.z*s.z);
        v[4*m+3] = PACK2(a.w*s.w, b.w*s.w);
    }
    fwht16(v);
#pragma unroll
    for (int m = 0; m < 4; m++)
#pragma unroll
        for (int j = 0; j < 4; j++)
            sm[SWZ(4*t + j + 1024*m)] = v[4*m + j];
    __syncthreads();

    // ---- P2: layout Y (bits 2..5) ----
    {
        int base = (t & 3) + ((t >> 2) << 6);
#pragma unroll
        for (int k = 0; k < 16; k++) v[k] = sm[SWZ(base + (k << 2))];
        fwht16(v);
#pragma unroll
        for (int k = 0; k < 16; k++) sm[SWZ(base + (k << 2))] = v[k];
    }
    __syncthreads();

    // ---- P3: layout Z (bits 6..9): FWHT1 tail + g + FWHT2 head ----
    {
        int base = (t & 63) + ((t >> 6) << 10);
#pragma unroll
        for (int k = 0; k < 16; k++) v[k] = sm[SWZ(base + (k << 6))];
        fwht16(v);
#pragma unroll
        for (int k = 0; k < 16; k++) {
            float gv = g_dev[base + (k << 6)];
            v[k] = MUL2(v[k], PACK2(gv, gv));
        }
        fwht16(v);
#pragma unroll
        for (int k = 0; k < 16; k++) sm[SWZ(base + (k << 6))] = v[k];
    }
    __syncthreads();

    // ---- P4: layout Y again ----
    {
        int base = (t & 3) + ((t >> 2) << 6);
#pragma unroll
        for (int k = 0; k < 16; k++) v[k] = sm[SWZ(base + (k << 2))];
        fwht16(v);
#pragma unroll
        for (int k = 0; k < 16; k++) sm[SWZ(base + (k << 2))] = v[k];
    }
    __syncthreads();

    // ---- P5: layout X, FWHT tail + s1 + coalesced store ----
    {
#pragma unroll
        for (int m = 0; m < 4; m++)
#pragma unroll
            for (int j = 0; j < 4; j++)
                v[4*m + j] = sm[SWZ(4*t + j + 1024*m)];
        fwht16(v);
        float* oa = out + rowA * DD;
        float* ob = oa + DD;
#pragma unroll
        for (int m = 0; m < 4; m++) {
            int base = 4*t + 1024*m;
            float4 s = *reinterpret_cast<const float4*>(s1 + base);
            float2 p0 = UNPK(MUL2(v[4*m+0], PACK2(s.x, s.x)));
            float2 p1 = UNPK(MUL2(v[4*m+1], PACK2(s.y, s.y)));
            float2 p2 = UNPK(MUL2(v[4*m+2], PACK2(s.z, s.z)));
            float2 p3 = UNPK(MUL2(v[4*m+3], PACK2(s.w, s.w)));
            *reinterpret_cast<float4*>(oa + base) = make_float4(p0.x, p1.x, p2.x, p3.x);
            *reinterpret_cast<float4*>(ob + base) = make_float4(p0.y, p1.y, p2.y, p3.y);
        }
    }
}

extern "C" void kernel_launch(void* const* d_in, const int* in_sizes, int n_in,
                              void* d_out, int out_size) {
    const float* x     = (const float*)d_in[0];
    const float* eps   = (const float*)d_in[1];
    const float* s1    = (const float*)d_in[2];
    const float* s2    = (const float*)d_in[3];
    const float* g_mu  = (const float*)d_in[4];
    const float* g_rho = (const float*)d_in[5];
    float* out = (float*)d_out;

    int B = in_sizes[0] / DD;   // 2048

    compute_g_kernel<<<(DD + 255) / 256, 256>>>(eps, g_mu, g_rho);
    whvi_kernel<<<B / 2, 256>>>(x, s1, s2, out);
}